// round 11
// baseline (speedup 1.0000x reference)
#include <cuda_runtime.h>
#include <cstdint>

// Shape (fixed): u[B=16, T=1024, H=2048] f32, alpha[H], beta[H], seed int32
#define BB 16
#define TT 1024
#define HH 2048
#define HC 8            // channels per CTA (= warps per CTA), kernel 1
#define NTHR 256
#define FULLM 0xFFFFFFFFu

#define TILE_FLOATS (TT * HC)    // 8192 floats = 32 KB

// XOR-swizzled tile layout (see R4): conflict-free column gathers.
__device__ __forceinline__ int swz(int t, int c) {
    int L = t >> 5;
    return (L << 8) + ((((t & 31) << 3) + c) ^ L);
}

__device__ __forceinline__ unsigned rotl32(unsigned x, int r) {
    return __funnelshift_l(x, x, r);
}

// XLA f32 tanh (Eigen generic_fast_tanh_float), plain mul/add (no contraction).
__device__ __forceinline__ float tanh_xla(float x) {
    float ax = fabsf(x);
    float xc = fminf(fmaxf(x, -7.90531110763549805f), 7.90531110763549805f);
    float x2 = __fmul_rn(xc, xc);
    float np = __fadd_rn(__fmul_rn(x2, -2.76076847742355e-16f), 2.00018790482477e-13f);
    np = __fadd_rn(__fmul_rn(x2, np), -8.60467152213735e-11f);
    np = __fadd_rn(__fmul_rn(x2, np),  5.12229709037114e-08f);
    np = __fadd_rn(__fmul_rn(x2, np),  1.48572235717979e-05f);
    np = __fadd_rn(__fmul_rn(x2, np),  6.37261928875436e-04f);
    np = __fadd_rn(__fmul_rn(x2, np),  4.89352455891786e-03f);
    float num = __fmul_rn(xc, np);
    float dp = __fadd_rn(__fmul_rn(x2, 1.19825839466702e-06f), 1.18534705686654e-04f);
    dp = __fadd_rn(__fmul_rn(x2, dp), 2.26843463243900e-03f);
    dp = __fadd_rn(__fmul_rn(x2, dp), 4.89352518554385e-03f);
    float t = __fdiv_rn(num, dp);
    return (ax < 0.0004f) ? x : t;
}

// Exact jax.lax.associative_scan tree over 1024 elems/channel:
// in-place register Blelloch (levels 0-4) + warp-shuffle Blelloch (5-9).
__device__ __forceinline__ void tree_scan(float (&v)[32], const float* A, int lane) {
    #pragma unroll
    for (int s = 0; s < 5; s++) {
        const int h = 1 << s, st = h << 1;
        #pragma unroll
        for (int p = st - 1; p < 32; p += st)
            v[p] = __fadd_rn(__fmul_rn(A[s], v[p - h]), v[p]);
    }
    float w = v[31];
    #pragma unroll
    for (int m = 0; m < 5; m++) {
        float t = __shfl_up_sync(FULLM, w, 1 << m);
        if ((lane & ((2 << m) - 1)) == ((2 << m) - 1))
            w = __fadd_rn(__fmul_rn(A[5 + m], t), w);
    }
    #pragma unroll
    for (int m = 3; m >= 0; m--) {
        float t = __shfl_up_sync(FULLM, w, 1 << m);
        if (((lane & ((2 << m) - 1)) == ((1 << m) - 1)) && (lane >= (2 << m)))
            w = __fadd_rn(__fmul_rn(A[5 + m], t), w);
    }
    float P = __shfl_up_sync(FULLM, w, 1);
    if (lane == 0) P = 0.0f;
    v[31] = w;
    #pragma unroll
    for (int s = 4; s >= 0; s--) {
        const int h = 1 << s, st = h << 1;
        #pragma unroll
        for (int p = h - 1; p < 32; p += st) {
            float left = (p < st) ? P : v[p - h];
            v[p] = __fadd_rn(__fmul_rn(A[s], left), v[p]);
        }
    }
}

// ===================== Kernel 1: cascaded scans, V -> out =====================
__global__ void __launch_bounds__(NTHR, 4)
scan_kernel(const float* __restrict__ u,
            const float* __restrict__ alpha,
            const float* __restrict__ beta,
            float* __restrict__ out) {
    __shared__ float S[TILE_FLOATS];                 // 32 KB

    const int tid  = threadIdx.x;
    const int lane = tid & 31;
    const int wrp  = tid >> 5;
    const int b    = blockIdx.x >> 8;
    const int h0   = (blockIdx.x & 255) * HC;

    // stage u tile [T][8] into swizzled smem (coalesced float4 loads)
    const float4* up4 = reinterpret_cast<const float4*>(u + ((size_t)b * TT) * HH + h0);
    #pragma unroll
    for (int k = 0; k < TILE_FLOATS / 4 / NTHR; k++) {   // 8 iters
        int i4 = k * NTHR + tid;
        int t = i4 >> 1, q = i4 & 1;
        float4 d = up4[(size_t)t * (HH / 4) + q];
        int c0 = q * 4;
        S[swz(t, c0 + 0)] = d.x;
        S[swz(t, c0 + 1)] = d.y;
        S[swz(t, c0 + 2)] = d.z;
        S[swz(t, c0 + 3)] = d.w;
    }
    __syncthreads();

    // gather 32 time steps of channel wrp (conflict-free)
    float v[32];
    #pragma unroll
    for (int j = 0; j < 32; j++)
        v[j] = S[(lane << 8) + (((j << 3) + wrp) ^ lane)];

    // decay powers + two scans (bit-exact vs JAX)
    float A[10];
    A[0] = fminf(fmaxf(alpha[h0 + wrp], 0.0f), 1.0f);
    #pragma unroll
    for (int s = 1; s < 10; s++) A[s] = __fmul_rn(A[s - 1], A[s - 1]);
    tree_scan(v, A, lane);                // synaptic current

    A[0] = fminf(fmaxf(beta[h0 + wrp], 0.0f), 1.0f);
    #pragma unroll
    for (int s = 1; s < 10; s++) A[s] = __fmul_rn(A[s - 1], A[s - 1]);
    tree_scan(v, A, lane);                // membrane potential V

    // write V back to smem, then densely to out (coalesced float4)
    #pragma unroll
    for (int j = 0; j < 32; j++)
        S[(lane << 8) + (((j << 3) + wrp) ^ lane)] = v[j];
    __syncthreads();

    float* outp = out + ((size_t)b * TT) * HH + h0;
    #pragma unroll
    for (int k = 0; k < TILE_FLOATS / 4 / NTHR; k++) {
        int i4 = k * NTHR + tid;
        int t = i4 >> 1, q = i4 & 1;
        int c0 = q * 4;
        float4 o;
        o.x = S[swz(t, c0 + 0)];
        o.y = S[swz(t, c0 + 1)];
        o.z = S[swz(t, c0 + 2)];
        o.w = S[swz(t, c0 + 3)];
        *reinterpret_cast<float4*>(outp + (size_t)t * HH + c0) = o;
    }
}

// ============ Kernel 2: in-place spike transform (V in out -> 0/1) ============
// Each warp owns 128 contiguous flat elements; CTA owns 1024. No __syncthreads.
__global__ void __launch_bounds__(NTHR)
spike_kernel(float* __restrict__ data,          // aliases out; holds V on entry
             const int* __restrict__ seedp) {
    __shared__ float         Vs[NTHR * 4];      // 4 KB: warp-local V copies
    __shared__ unsigned char Lst[HC][128];      // 1 KB: warp-local u8 index lists
    __shared__ unsigned int  Flg[HC][32];       // 1 KB: spike flags (byte per elem)

    const int tid  = threadIdx.x;
    const int lane = tid & 31;
    const int wrp  = tid >> 5;
    const unsigned wbase = (unsigned)blockIdx.x * (NTHR * 4) + (unsigned)wrp * 128;

    // dense coalesced V load (element base = wbase + lane*4)
    float4 v4 = reinterpret_cast<const float4*>(data)[(size_t)blockIdx.x * NTHR + tid];
    reinterpret_cast<float4*>(Vs)[tid] = v4;
    Flg[wrp][lane] = 0u;

    // register gate (frozen conservative sign-of-cos bound) + warp compaction.
    // p>0 <=> cosf(2pi*U)>0; |U-round(U)| < fma(|U|,4e-7,0.252) over-covers all
    // rounding; over-inclusion safe (Phase B computes exact p).
    float vv[4] = {v4.x, v4.y, v4.z, v4.w};
    int cnt = 0;
    #pragma unroll
    for (int i = 0; i < 4; i++) {
        float U = __fadd_rn(vv[i], -1.0f);
        float w = __fadd_rn(U, -rintf(U));           // exact (Sterbenz)
        bool act = fabsf(w) < __fmaf_rn(fabsf(U), 4e-7f, 0.252f);
        unsigned mask = __ballot_sync(FULLM, act);
        if (act) {
            int pos = cnt + __popc(mask & ((1u << lane) - 1u));
            Lst[wrp][pos] = (unsigned char)(lane * 4 + i);
        }
        cnt += __popc(mask);
    }
    int total = cnt;
    __syncwarp();    // order Vs/Lst stores before cross-lane reads

    // Phase B: bit-exact p + threefry on survivors, 2-wide ILP.
    const unsigned k2   = (unsigned)seedp[0];    // key=(0,seed): ks0=0
    const unsigned ks1  = k2;
    const unsigned ks2v = k2 ^ 0x1BD11BDAu;

    for (int s0 = 0; s0 < total; s0 += 64) {
        int r0 = s0 + lane, r1 = s0 + 32 + lane;
        bool a0 = r0 < total, a1 = r1 < total;
        int idx0 = (int)Lst[wrp][a0 ? r0 : total - 1];
        int idx1 = (int)Lst[wrp][a1 ? r1 : total - 1];

        float V0 = Vs[wrp * 128 + idx0];
        float V1 = Vs[wrp * 128 + idx1];
        float U0 = __fadd_rn(V0, -1.0f);
        float U1 = __fadd_rn(V1, -1.0f);
        float cv0 = cosf(__fmul_rn(6.2831855f, U0));
        float cv1 = cosf(__fmul_rn(6.2831855f, U1));
        float th0 = tanh_xla(__fmul_rn(50.0f, U0));
        float th1 = tanh_xla(__fmul_rn(50.0f, U1));
        float p0 = fmaxf(__fmul_rn(cv0, __fadd_rn(__fmul_rn(0.5f, th0), 0.5f)), 0.0f);
        float p1 = fmaxf(__fmul_rn(cv1, __fadd_rn(__fmul_rn(0.5f, th1), 0.5f)), 0.0f);

        unsigned g0 = wbase + (unsigned)idx0;
        unsigned g1 = wbase + (unsigned)idx1;

        // threefry2x32(key=(0,seed), counts=(0, gi)); fold out0^out1
        unsigned x0 = 0u, x1 = g0 + ks1;
        unsigned y0 = 0u, y1 = g1 + ks1;
        #define TFR2(r_) { x0 += x1; y0 += y1; \
                           x1 = rotl32(x1, (r_)); y1 = rotl32(y1, (r_)); \
                           x1 ^= x0; y1 ^= y0; }
        TFR2(13) TFR2(15) TFR2(26) TFR2(6)
        x0 += ks1;  x1 += ks2v + 1u;   y0 += ks1;  y1 += ks2v + 1u;
        TFR2(17) TFR2(29) TFR2(16) TFR2(24)
        x0 += ks2v; x1 += 2u;          y0 += ks2v; y1 += 2u;
        TFR2(13) TFR2(15) TFR2(26) TFR2(6)
        x1 += ks1 + 3u;                y1 += ks1 + 3u;
        TFR2(17) TFR2(29) TFR2(16) TFR2(24)
        x0 += ks1;  x1 += ks2v + 4u;   y0 += ks1;  y1 += ks2v + 4u;
        TFR2(13) TFR2(15) TFR2(26) TFR2(6)
        x0 += ks2v; x1 += 5u;          y0 += ks2v; y1 += 5u;
        #undef TFR2
        float uf0 = __fadd_rn(__uint_as_float((((x0 ^ x1) >> 9) | 0x3F800000u)), -1.0f);
        float uf1 = __fadd_rn(__uint_as_float((((y0 ^ y1) >> 9) | 0x3F800000u)), -1.0f);

        unsigned char* fb = reinterpret_cast<unsigned char*>(&Flg[wrp][0]);
        if (a0 && uf0 < p0) fb[idx0] = 1;
        if (a1 && uf1 < p1) fb[idx1] = 1;
    }
    __syncwarp();    // flags visible warp-wide

    // dense coalesced 0/1 store (overwrites V in place; warp-local region)
    unsigned fw = Flg[wrp][lane];
    float4 o;
    o.x = (fw & 0x000000FFu) ? 1.0f : 0.0f;
    o.y = (fw & 0x0000FF00u) ? 1.0f : 0.0f;
    o.z = (fw & 0x00FF0000u) ? 1.0f : 0.0f;
    o.w = (fw & 0xFF000000u) ? 1.0f : 0.0f;
    reinterpret_cast<float4*>(data)[(size_t)blockIdx.x * NTHR + tid] = o;
}

extern "C" void kernel_launch(void* const* d_in, const int* in_sizes, int n_in,
                              void* d_out, int out_size) {
    const float* u     = (const float*)d_in[0];
    const float* alpha = (const float*)d_in[1];
    const float* beta  = (const float*)d_in[2];
    const int*   seed  = (const int*)d_in[3];
    float* out = (float*)d_out;
    (void)in_sizes; (void)n_in; (void)out_size;

    dim3 grid1(BB * (HH / HC));                        // 4096 CTAs
    scan_kernel<<<grid1, NTHR>>>(u, alpha, beta, out); // out <- V
    dim3 grid2((BB * TT * HH) / (NTHR * 4));           // 32768 CTAs
    spike_kernel<<<grid2, NTHR>>>(out, seed);          // out <- spikes (in place)
}

// round 12
// speedup vs baseline: 1.4974x; 1.4974x over previous
#include <cuda_runtime.h>
#include <cstdint>

// Shape (fixed): u[B=16, T=1024, H=2048] f32, alpha[H], beta[H], seed int32
#define BB 16
#define TT 1024
#define HH 2048
#define HC 8            // channels per CTA (= warps per CTA)
#define NTHR 256
#define FULLM 0xFFFFFFFFu

#define TILE_FLOATS (TT * HC)    // 8192 floats = 32 KB

// XOR-swizzled tile layout (see R4): conflict-free column gathers.
__device__ __forceinline__ int swz(int t, int c) {
    int L = t >> 5;
    return (L << 8) + ((((t & 31) << 3) + c) ^ L);
}

__device__ __forceinline__ unsigned rotl32(unsigned x, int r) {
    return __funnelshift_l(x, x, r);
}

// XLA f32 tanh (Eigen generic_fast_tanh_float), plain mul/add (no contraction).
__device__ __forceinline__ float tanh_xla(float x) {
    float ax = fabsf(x);
    float xc = fminf(fmaxf(x, -7.90531110763549805f), 7.90531110763549805f);
    float x2 = __fmul_rn(xc, xc);
    float np = __fadd_rn(__fmul_rn(x2, -2.76076847742355e-16f), 2.00018790482477e-13f);
    np = __fadd_rn(__fmul_rn(x2, np), -8.60467152213735e-11f);
    np = __fadd_rn(__fmul_rn(x2, np),  5.12229709037114e-08f);
    np = __fadd_rn(__fmul_rn(x2, np),  1.48572235717979e-05f);
    np = __fadd_rn(__fmul_rn(x2, np),  6.37261928875436e-04f);
    np = __fadd_rn(__fmul_rn(x2, np),  4.89352455891786e-03f);
    float num = __fmul_rn(xc, np);
    float dp = __fadd_rn(__fmul_rn(x2, 1.19825839466702e-06f), 1.18534705686654e-04f);
    dp = __fadd_rn(__fmul_rn(x2, dp), 2.26843463243900e-03f);
    dp = __fadd_rn(__fmul_rn(x2, dp), 4.89352518554385e-03f);
    float t = __fdiv_rn(num, dp);
    return (ax < 0.0004f) ? x : t;
}

// Exact jax.lax.associative_scan tree over 1024 elems/channel:
// in-place register Blelloch (levels 0-4) + warp-shuffle Blelloch (5-9).
__device__ __forceinline__ void tree_scan(float (&v)[32], const float* A, int lane) {
    #pragma unroll
    for (int s = 0; s < 5; s++) {
        const int h = 1 << s, st = h << 1;
        #pragma unroll
        for (int p = st - 1; p < 32; p += st)
            v[p] = __fadd_rn(__fmul_rn(A[s], v[p - h]), v[p]);
    }
    float w = v[31];
    #pragma unroll
    for (int m = 0; m < 5; m++) {
        float t = __shfl_up_sync(FULLM, w, 1 << m);
        if ((lane & ((2 << m) - 1)) == ((2 << m) - 1))
            w = __fadd_rn(__fmul_rn(A[5 + m], t), w);
    }
    #pragma unroll
    for (int m = 3; m >= 0; m--) {
        float t = __shfl_up_sync(FULLM, w, 1 << m);
        if (((lane & ((2 << m) - 1)) == ((1 << m) - 1)) && (lane >= (2 << m)))
            w = __fadd_rn(__fmul_rn(A[5 + m], t), w);
    }
    float P = __shfl_up_sync(FULLM, w, 1);
    if (lane == 0) P = 0.0f;
    v[31] = w;
    #pragma unroll
    for (int s = 4; s >= 0; s--) {
        const int h = 1 << s, st = h << 1;
        #pragma unroll
        for (int p = h - 1; p < 32; p += st) {
            float left = (p < st) ? P : v[p - h];
            v[p] = __fadd_rn(__fmul_rn(A[s], left), v[p]);
        }
    }
}

// Full bit-exact spike decision for one gated element of channel c=wrp.
__device__ __forceinline__ void spike_eval(const float* S, int t, int c,
                                           unsigned CbaseC, unsigned ks1, unsigned ks2v,
                                           unsigned& gi, bool& spk) {
    float V = S[swz(t, c)];
    float U = __fadd_rn(V, -1.0f);                       // V - THRESHOLD
    float cv  = cosf(__fmul_rn(6.2831855f, U));          // cos(f32(2pi)*U)
    float th  = tanh_xla(__fmul_rn(50.0f, U));           // logistic(100U)
    float sig = __fadd_rn(__fmul_rn(0.5f, th), 0.5f);
    float p   = fmaxf(__fmul_rn(cv, sig), 0.0f);

    gi = CbaseC + (unsigned)t * (unsigned)HH;

    // threefry2x32(key=(0,seed), counts=(0, gi)); fold out0^out1
    unsigned x0 = 0u;
    unsigned x1 = gi + ks1;
    #define TFR(r_) { x0 += x1; x1 = rotl32(x1, (r_)); x1 ^= x0; }
    TFR(13) TFR(15) TFR(26) TFR(6)   x0 += ks1;  x1 += ks2v + 1u;
    TFR(17) TFR(29) TFR(16) TFR(24)  x0 += ks2v; x1 += 2u;
    TFR(13) TFR(15) TFR(26) TFR(6)                x1 += ks1 + 3u;
    TFR(17) TFR(29) TFR(16) TFR(24)  x0 += ks1;  x1 += ks2v + 4u;
    TFR(13) TFR(15) TFR(26) TFR(6)   x0 += ks2v; x1 += 5u;
    #undef TFR
    unsigned bits = x0 ^ x1;
    float uf = __fadd_rn(__uint_as_float((bits >> 9) | 0x3F800000u), -1.0f);
    spk = (uf < p);
}

__global__ void __launch_bounds__(NTHR, 4)   // pin <=64 regs (occupancy knee)
cubalif_kernel(const float* __restrict__ u,
               const float* __restrict__ alpha,
               const float* __restrict__ beta,
               const int*   __restrict__ seedp,
               float* __restrict__ out) {
    __shared__ float S[TILE_FLOATS];                 // 32 KB (V values)
    __shared__ unsigned short Lst[TILE_FLOATS];      // 16 KB compacted t-indices

    const int tid  = threadIdx.x;
    const int lane = tid & 31;
    const int wrp  = tid >> 5;            // warp id in CTA = channel (scan & spike)
    const int b    = blockIdx.x >> 8;
    const int h0   = (blockIdx.x & 255) * HC;

    // ---- stage u tile [T][8] into swizzled smem + zero-fill out tile ----
    const float4* up4 = reinterpret_cast<const float4*>(u + ((size_t)b * TT) * HH + h0);
    float* outp = out + ((size_t)b * TT) * HH + h0;
    const float4 z4 = make_float4(0.f, 0.f, 0.f, 0.f);
    #pragma unroll
    for (int k = 0; k < TILE_FLOATS / 4 / NTHR; k++) {   // 8 iters
        int i4 = k * NTHR + tid;
        int t = i4 >> 1, q = i4 & 1;
        float4 d = up4[(size_t)t * (HH / 4) + q];
        int c0 = q * 4;
        S[swz(t, c0 + 0)] = d.x;
        S[swz(t, c0 + 1)] = d.y;
        S[swz(t, c0 + 2)] = d.z;
        S[swz(t, c0 + 3)] = d.w;
        *reinterpret_cast<float4*>(outp + (size_t)t * HH + c0) = z4;
    }
    __syncthreads();

    // ---- gather 32 time steps of channel wrp (conflict-free) ----
    float v[32];
    #pragma unroll
    for (int j = 0; j < 32; j++)
        v[j] = S[(lane << 8) + (((j << 3) + wrp) ^ lane)];

    // ---- decay powers + two scans (bit-exact vs JAX) ----
    float A[10];
    A[0] = fminf(fmaxf(alpha[h0 + wrp], 0.0f), 1.0f);
    #pragma unroll
    for (int s = 1; s < 10; s++) A[s] = __fmul_rn(A[s - 1], A[s - 1]);
    tree_scan(v, A, lane);                // synaptic current

    A[0] = fminf(fmaxf(beta[h0 + wrp], 0.0f), 1.0f);
    #pragma unroll
    for (int s = 1; s < 10; s++) A[s] = __fmul_rn(A[s - 1], A[s - 1]);
    tree_scan(v, A, lane);                // membrane potential V

    // ===== Phase A (register-resident, channel-sliced): gate mask + prefix =====
    // p > 0  <=>  cosf(2pi*U) > 0  (Eigen-sigmoid strictly positive).
    // cos>0 <=> |U - round(U)| < 0.25 up to rounding; margin fma(|U|,4e-7,.252)
    // over-covers all rounding paths. Over-inclusion safe (Phase B exact).
    unsigned gm = 0u;                     // lane-private gate mask over j=0..31
    #pragma unroll
    for (int j = 0; j < 32; j++) {
        float U = __fadd_rn(v[j], -1.0f);
        float w = __fadd_rn(U, -rintf(U));           // exact (Sterbenz)
        if (fabsf(w) < __fmaf_rn(fabsf(U), 4e-7f, 0.252f)) gm |= (1u << j);
    }
    int cnt  = __popc(gm);
    int incl = cnt;
    #pragma unroll
    for (int s = 1; s < 32; s <<= 1) {
        int tsh = __shfl_up_sync(FULLM, incl, s);
        if (lane >= s) incl += tsh;
    }
    int myoff = incl - cnt;                          // exclusive prefix
    int total = __shfl_sync(FULLM, incl, 31);

    // ---- writeback V + fused index emission (v dies here, as in R10) ----
    const int wtile = wrp << 10;
    #pragma unroll
    for (int j = 0; j < 32; j++) {
        S[(lane << 8) + (((j << 3) + wrp) ^ lane)] = v[j];
        if (gm & (1u << j)) { Lst[wtile + myoff] = (unsigned short)(lane * 32 + j); myoff++; }
    }
    __syncwarp();   // own-warp STS (S channel slots + Lst) -> cross-lane LDS

    // ===== Phase B: 2-wide ILP — two independent gated chains per thread =====
    const unsigned k2   = (unsigned)seedp[0];    // key=(0,seed): ks0=0
    const unsigned ks1  = k2;
    const unsigned ks2v = k2 ^ 0x1BD11BDAu;
    const unsigned CbaseC = (unsigned)(b * TT) * (unsigned)HH + (unsigned)(h0 + wrp);

    for (int s0 = 0; s0 < total; s0 += 64) {
        int r0 = s0 + lane;
        int r1 = s0 + 32 + lane;
        bool a0 = r0 < total, a1 = r1 < total;
        int t0 = (int)Lst[wtile + (a0 ? r0 : total - 1)];
        int t1 = (int)Lst[wtile + (a1 ? r1 : total - 1)];
        unsigned gi0, gi1; bool s0k, s1k;
        spike_eval(S, t0, wrp, CbaseC, ks1, ks2v, gi0, s0k);
        spike_eval(S, t1, wrp, CbaseC, ks1, ks2v, gi1, s1k);
        if (a0 && s0k) out[gi0] = 1.0f;   // overwrite the zero
        if (a1 && s1k) out[gi1] = 1.0f;   // (dup lanes write same value: benign)
    }
}

extern "C" void kernel_launch(void* const* d_in, const int* in_sizes, int n_in,
                              void* d_out, int out_size) {
    const float* u     = (const float*)d_in[0];
    const float* alpha = (const float*)d_in[1];
    const float* beta  = (const float*)d_in[2];
    const int*   seed  = (const int*)d_in[3];
    float* out = (float*)d_out;
    (void)in_sizes; (void)n_in; (void)out_size;

    dim3 grid(BB * (HH / HC));   // 4096 CTAs
    cubalif_kernel<<<grid, NTHR>>>(u, alpha, beta, seed, out);
}